// round 15
// baseline (speedup 1.0000x reference)
#include <cuda_runtime.h>
#include <cstdint>
#include <cstddef>

// Problem dims
#define BB   128      // batch
#define SS   200      // seq
#define VV   1400     // vocab
#define DD   256      // input/hidden dim
#define HH   256
#define G4   1024     // 4*H
#define NC   128      // classes

#define NBLK 128      // recurrence grid (co-resident, cooperative launch)

// ---------------- packed fp32 (f32x2 / SASS FFMA2) helpers ----------------
#define FMA2(acc, a, b) \
    asm("fma.rn.f32x2 %0, %1, %2, %0;" : "+l"(acc) : "l"(a), "l"(b))
#define ADD2(acc, a) \
    asm("add.rn.f32x2 %0, %0, %1;" : "+l"(acc) : "l"(a))
#define DUP2(out, f) \
    do { unsigned int _u = __float_as_uint(f); \
         asm("mov.b64 %0, {%1, %1};" : "=l"(out) : "r"(_u)); } while (0)
__device__ __forceinline__ float lo2(unsigned long long v) {
    return __uint_as_float((unsigned int)v);
}
__device__ __forceinline__ float hi2(unsigned long long v) {
    return __uint_as_float((unsigned int)(v >> 32));
}

// ---------------- device scratch (static, no allocs) ----------------
__device__ __align__(16) float g_embedded[BB * SS * DD];   // [b][s][d]
__device__ __align__(16) float g_ux[2][SS * G4 * BB];      // [l][s][e][b]
__device__ __align__(16) float g_hs[2][SS * HH * BB];      // [l][t][j][b]
// state: plain [k][b] layout, b contiguous (rows of 128 floats)
__device__ __align__(16) float g_hbuf[2][2][HH * BB];      // [phase][l][k*128+b]
__device__ __align__(16) float g_cbuf[2][2][HH * BB];
__device__ __align__(16) float g_tsT[SS * BB];             // [t][b]
__device__ __align__(16) float g_alpha[BB * SS];
__device__ __align__(16) float g_beta[SS * DD * BB];       // [s][d][b]
__device__ __align__(16) float g_ctx[BB * DD];
__device__ unsigned g_bar_count;
__device__ volatile unsigned g_bar_phase;

// ---------------- helpers ----------------
__device__ __forceinline__ float sigf(float x) { return 1.0f / (1.0f + __expf(-x)); }

// grid barrier, NBLK co-resident blocks (cooperative launch guarantees residency).
// bar.sync cumulativity + thread0 gpu fence (CG grid.sync pattern): no per-thread fences.
__device__ __forceinline__ void gridbar(unsigned target) {
    __syncthreads();
    if (threadIdx.x == 0) {
        __threadfence();
        unsigned old = atomicAdd(&g_bar_count, 1u);
        if (old == NBLK - 1u) {
            atomicExch(&g_bar_count, 0u);
            __threadfence();
            g_bar_phase = target;
        } else {
            while (g_bar_phase < target) { __nanosleep(32); }
        }
        __threadfence();
    }
    __syncthreads();
}

// ---------------- init: barrier reset, state transpose, ts transpose ----------------
__global__ void init_kernel(const float* __restrict__ h01, const float* __restrict__ c01,
                            const float* __restrict__ h02, const float* __restrict__ c02,
                            const float* __restrict__ tsp) {
    int gid = blockIdx.x * blockDim.x + threadIdx.x;
    int stride = gridDim.x * blockDim.x;
    if (gid == 0) { g_bar_count = 0u; g_bar_phase = 0u; }
    for (int i = gid; i < HH * BB; i += stride) {
        int k = i >> 7, b = i & 127;        // dst [k][b] <- src [b][k]
        g_hbuf[0][0][i] = h01[b * HH + k];
        g_cbuf[0][0][i] = c01[b * HH + k];
        g_hbuf[0][1][i] = h02[b * HH + k];
        g_cbuf[0][1][i] = c02[b * HH + k];
    }
    for (int i = gid; i < SS * BB; i += stride) {
        int t = i >> 7, b = i & 127;
        g_tsT[i] = tsp[b * SS + t];
    }
}

// ---------------- K1: embedded = inputs @ emb ----------------
__global__ __launch_bounds__(256) void embed_gemm(const float* __restrict__ A,
                                                  const float* __restrict__ W) {
    const int m0 = blockIdx.y * 128;
    const int n0 = blockIdx.x * 64;
    __shared__ __align__(16) float As[8][128];
    __shared__ __align__(16) float Bs[8][64];
    const int tid = threadIdx.x;
    const int a_m = tid >> 1, a_k = (tid & 1) * 4;
    const int b_k = tid >> 5, b_n = (tid & 31) * 2;
    const int tx = tid & 15, ty = tid >> 4;
    unsigned long long accp[4][4];
#pragma unroll
    for (int ip = 0; ip < 4; ++ip)
#pragma unroll
        for (int jx = 0; jx < 4; ++jx) accp[ip][jx] = 0ULL;

    const float* Ap = A + (size_t)(m0 + a_m) * VV + a_k;
    const float* Bp = W + (size_t)b_k * DD + n0 + b_n;

    for (int k0 = 0; k0 < VV; k0 += 8) {
        float4 av = *(const float4*)(Ap + k0);
        float2 bv = *(const float2*)(Bp + (size_t)k0 * DD);
        __syncthreads();
        As[a_k + 0][a_m] = av.x; As[a_k + 1][a_m] = av.y;
        As[a_k + 2][a_m] = av.z; As[a_k + 3][a_m] = av.w;
        Bs[b_k][b_n] = bv.x; Bs[b_k][b_n + 1] = bv.y;
        __syncthreads();
#pragma unroll
        for (int k = 0; k < 8; ++k) {
            const unsigned long long* ap = (const unsigned long long*)&As[k][ty * 8];
            const float* bqf = &Bs[k][tx * 4];
            unsigned long long b2[4];
            DUP2(b2[0], bqf[0]); DUP2(b2[1], bqf[1]);
            DUP2(b2[2], bqf[2]); DUP2(b2[3], bqf[3]);
#pragma unroll
            for (int ip = 0; ip < 4; ++ip) {
                unsigned long long a2 = ap[ip];
#pragma unroll
                for (int jx = 0; jx < 4; ++jx) FMA2(accp[ip][jx], a2, b2[jx]);
            }
        }
    }
#pragma unroll
    for (int ip = 0; ip < 4; ++ip) {
        float4 v0 = make_float4(lo2(accp[ip][0]), lo2(accp[ip][1]),
                                lo2(accp[ip][2]), lo2(accp[ip][3]));
        float4 v1 = make_float4(hi2(accp[ip][0]), hi2(accp[ip][1]),
                                hi2(accp[ip][2]), hi2(accp[ip][3]));
        int m = m0 + ty * 8 + 2 * ip;
        *(float4*)&g_embedded[(size_t)m * DD + n0 + tx * 4] = v0;
        *(float4*)&g_embedded[(size_t)(m + 1) * DD + n0 + tx * 4] = v1;
    }
}

// ---------------- K2: ux[l][s][e][b] = U_l @ embedded_s^T + (Uall_b + Wall_b) ----------------
__global__ __launch_bounds__(256) void ux_gemm(
    const float* __restrict__ U1, const float* __restrict__ Ub1, const float* __restrict__ Wb1,
    const float* __restrict__ U2, const float* __restrict__ Ub2, const float* __restrict__ Wb2) {
    const int l = blockIdx.z / SS;
    const int s = blockIdx.z % SS;
    const float* U  = l ? U2  : U1;
    const float* bu = l ? Ub2 : Ub1;
    const float* bw = l ? Wb2 : Wb1;
    const int e0 = blockIdx.y * 128;
    const int n0 = blockIdx.x * 64;
    __shared__ __align__(16) float As[16][128];
    __shared__ __align__(16) float Bs[16][64];
    const int tid = threadIdx.x;
    const int a_m = tid >> 1, a_k = (tid & 1) * 8;
    const int b_n = tid >> 2, b_k = (tid & 3) * 4;
    const int tx = tid & 15, ty = tid >> 4;
    unsigned long long accp[4][4];
#pragma unroll
    for (int ip = 0; ip < 4; ++ip)
#pragma unroll
        for (int jx = 0; jx < 4; ++jx) accp[ip][jx] = 0ULL;

    const float* Ap = U + (size_t)(e0 + a_m) * DD + a_k;
    const float* Bp = g_embedded + (size_t)(n0 + b_n) * (SS * DD) + s * DD + b_k;

    for (int k0 = 0; k0 < DD; k0 += 16) {
        float4 av0 = *(const float4*)(Ap + k0);
        float4 av1 = *(const float4*)(Ap + k0 + 4);
        float4 bv  = *(const float4*)(Bp + k0);
        __syncthreads();
        As[a_k + 0][a_m] = av0.x; As[a_k + 1][a_m] = av0.y;
        As[a_k + 2][a_m] = av0.z; As[a_k + 3][a_m] = av0.w;
        As[a_k + 4][a_m] = av1.x; As[a_k + 5][a_m] = av1.y;
        As[a_k + 6][a_m] = av1.z; As[a_k + 7][a_m] = av1.w;
        Bs[b_k + 0][b_n] = bv.x; Bs[b_k + 1][b_n] = bv.y;
        Bs[b_k + 2][b_n] = bv.z; Bs[b_k + 3][b_n] = bv.w;
        __syncthreads();
#pragma unroll
        for (int k = 0; k < 16; ++k) {
            const unsigned long long* ap = (const unsigned long long*)&As[k][ty * 8];
            const float* bqf = &Bs[k][tx * 4];
            unsigned long long b2[4];
            DUP2(b2[0], bqf[0]); DUP2(b2[1], bqf[1]);
            DUP2(b2[2], bqf[2]); DUP2(b2[3], bqf[3]);
#pragma unroll
            for (int ip = 0; ip < 4; ++ip) {
                unsigned long long a2 = ap[ip];
#pragma unroll
                for (int jx = 0; jx < 4; ++jx) FMA2(accp[ip][jx], a2, b2[jx]);
            }
        }
    }
    float* uxl = g_ux[l];
#pragma unroll
    for (int ip = 0; ip < 4; ++ip) {
        int e = e0 + ty * 8 + 2 * ip;
        float bias0 = bu[e] + bw[e];
        float bias1 = bu[e + 1] + bw[e + 1];
        float4 v0 = make_float4(lo2(accp[ip][0]) + bias0, lo2(accp[ip][1]) + bias0,
                                lo2(accp[ip][2]) + bias0, lo2(accp[ip][3]) + bias0);
        float4 v1 = make_float4(hi2(accp[ip][0]) + bias1, hi2(accp[ip][1]) + bias1,
                                hi2(accp[ip][2]) + bias1, hi2(accp[ip][3]) + bias1);
        *(float4*)&uxl[((size_t)s * G4 + e) * BB + n0 + tx * 4] = v0;
        *(float4*)&uxl[((size_t)s * G4 + e + 1) * BB + n0 + tx * 4] = v1;
    }
}

// ---------------- persistent recurrence: dup=1 state reads ----------------
// 128 blocks: l = blk>>6, unit group j0 = (blk&63)*4 (4 units).
// 512 threads: ks = tid>>6 (k-eighth, 32 k each), bp = tid&63 (batch pair b0=2*bp).
// Each thread computes partials for ALL 4 units x 5 gates over its (k-slice, batch pair):
// each state element is read from L2 exactly once per block (32 MB/step vs 128 MB before).
// Weights pre-duplicated in smem as (w,w) ullong pairs -> LDS.128 broadcast (k warp-uniform).
// 3-round smem tree reduction folds the 8 k-slices; tid<64 runs the gate epilogue.
// Dynamic smem: weights 40960 B + reduction buffer 256*21*8 = 43008 B.
__global__ __launch_bounds__(512, 1) void recur_kernel(
    const float* __restrict__ Wall1, const float* __restrict__ Wd1w, const float* __restrict__ Wd1b,
    const float* __restrict__ Wall2, const float* __restrict__ Wd2w, const float* __restrict__ Wd2b) {
    extern __shared__ unsigned long long dynsm[];
    unsigned long long* ws  = dynsm;          // [k][20] dup'd weights, 5120 ullong
    unsigned long long* buf = dynsm + 5120;   // reduction, 256 slots * 21 stride
    __shared__ float bds[4];

    const int l  = blockIdx.x >> 6;
    const int j0 = (blockIdx.x & 63) * 4;
    const float* Wall = l ? Wall2 : Wall1;
    const float* Wd   = l ? Wd2w : Wd1w;
    const float* Wdb  = l ? Wd2b : Wd1b;

    const int tid = threadIdx.x;
    // stage weights once: p = g*4+u for g<4 (F,I,O,C), p=16+u for D(Wd)
    for (int idx = tid; idx < 5120; idx += 512) {
        int k = idx / 20, p = idx % 20;
        float w;
        if (p < 16) {
            int g = p >> 2, u = p & 3;
            w = Wall[((size_t)((g << 8) + j0 + u)) * DD + k];
        } else {
            int u = p - 16;
            w = Wd[(size_t)(j0 + u) * DD + k];
        }
        DUP2(ws[idx], w);
    }
    if (tid < 4) bds[tid] = Wdb[j0 + tid];
    __syncthreads();

    const int ks = tid >> 6;               // 0..7
    const int bp = tid & 63;
    const int b0 = bp * 2;
    const int kbase = ks * 32;
    float* hs_l = g_hs[l];
    const float* ux_l = g_ux[l];

    for (int t = 0; t < SS; ++t) {
        gridbar((unsigned)(t + 1));

        const int pb = t & 1;
        const float* hp = g_hbuf[pb][l];
        const float* cp = g_cbuf[pb][l];
        float* hw = g_hbuf[pb ^ 1][l];
        float* cw = g_cbuf[pb ^ 1][l];

        // acc[p]: packed over (b0, b0+1). p = g*4+u (g<4), 16+u for D.
        unsigned long long acc[20];
#pragma unroll
        for (int p = 0; p < 20; ++p) acc[p] = 0ULL;

        const unsigned long long* hq = (const unsigned long long*)(hp + b0);
        const unsigned long long* cq = (const unsigned long long*)(cp + b0);

#pragma unroll 4
        for (int ki = 0; ki < 32; ++ki) {
            const int k = kbase + ki;
            unsigned long long h2 = __ldcg(hq + k * 64);   // (h[k][b0], h[k][b0+1])
            unsigned long long c2 = __ldcg(cq + k * 64);
            const ulonglong2* wp = (const ulonglong2*)(ws + k * 20);
#pragma unroll
            for (int j = 0; j < 8; ++j) {                   // gates F,I,O,C (16 accs)
                ulonglong2 w2 = wp[j];
                FMA2(acc[2 * j],     h2, w2.x);
                FMA2(acc[2 * j + 1], h2, w2.y);
            }
            {                                               // D (Wd · c), accs 16..19
                ulonglong2 w8 = wp[8], w9 = wp[9];
                FMA2(acc[16], c2, w8.x); FMA2(acc[17], c2, w8.y);
                FMA2(acc[18], c2, w9.x); FMA2(acc[19], c2, w9.y);
            }
        }

        // 3-round tree reduction over ks (8 -> 4 -> 2 -> 1)
        if (tid >= 256) {
            unsigned long long* dst = buf + (size_t)(tid - 256) * 21;
#pragma unroll
            for (int p = 0; p < 20; ++p) dst[p] = acc[p];
        }
        __syncthreads();
        if (tid < 256) {
            const unsigned long long* src = buf + (size_t)tid * 21;
#pragma unroll
            for (int p = 0; p < 20; ++p) ADD2(acc[p], src[p]);
        }
        __syncthreads();
        if (tid >= 128 && tid < 256) {
            unsigned long long* dst = buf + (size_t)(tid - 128) * 21;
#pragma unroll
            for (int p = 0; p < 20; ++p) dst[p] = acc[p];
        }
        __syncthreads();
        if (tid < 128) {
            const unsigned long long* src = buf + (size_t)tid * 21;
#pragma unroll
            for (int p = 0; p < 20; ++p) ADD2(acc[p], src[p]);
        }
        __syncthreads();
        if (tid >= 64 && tid < 128) {
            unsigned long long* dst = buf + (size_t)(tid - 64) * 21;
#pragma unroll
            for (int p = 0; p < 20; ++p) dst[p] = acc[p];
        }
        __syncthreads();

        if (tid < 64) {
            const unsigned long long* src = buf + (size_t)tid * 21;
#pragma unroll
            for (int p = 0; p < 20; ++p) ADD2(acc[p], src[p]);

            float2 ts2 = *(const float2*)(g_tsT + t * BB + b0);
#pragma unroll
            for (int u = 0; u < 4; ++u) {
                const int j = j0 + u;
                float sF0 = lo2(acc[0 + u]),  sF1 = hi2(acc[0 + u]);
                float sI0 = lo2(acc[4 + u]),  sI1 = hi2(acc[4 + u]);
                float sO0 = lo2(acc[8 + u]),  sO1 = hi2(acc[8 + u]);
                float sC0 = lo2(acc[12 + u]), sC1 = hi2(acc[12 + u]);
                float sD0 = lo2(acc[16 + u]), sD1 = hi2(acc[16 + u]);

                const float* uxp = ux_l + ((size_t)t * G4 + j) * BB + b0;
                float2 uf = __ldcs((const float2*)(uxp + 0 * 256 * BB));
                float2 ui = __ldcs((const float2*)(uxp + 1 * 256 * BB));
                float2 uo = __ldcs((const float2*)(uxp + 2 * 256 * BB));
                float2 uc = __ldcs((const float2*)(uxp + 3 * 256 * BB));
                float2 co = __ldcg((const float2*)(cp + j * BB + b0));
                const float bd = bds[u];

                float csx0 = tanhf(sD0 + bd), csx1 = tanhf(sD1 + bd);
                float ca0 = co.x + csx0 * (ts2.x - 1.0f);
                float ca1 = co.y + csx1 * (ts2.y - 1.0f);
                float f0 = sigf(sF0 + uf.x), f1 = sigf(sF1 + uf.y);
                float i0 = sigf(sI0 + ui.x), i1 = sigf(sI1 + ui.y);
                float o0 = sigf(sO0 + uo.x), o1 = sigf(sO1 + uo.y);
                float q0 = sigf(sC0 + uc.x), q1 = sigf(sC1 + uc.y);
                float cn0 = f0 * ca0 + i0 * q0, cn1 = f1 * ca1 + i1 * q1;
                float hn0 = o0 * tanhf(cn0),    hn1 = o1 * tanhf(cn1);

                *(float2*)(cw + j * BB + b0) = make_float2(cn0, cn1);
                *(float2*)(hw + j * BB + b0) = make_float2(hn0, hn1);
                *(float2*)(hs_l + ((size_t)t * HH + j) * BB + b0) = make_float2(hn0, hn1);
            }
        }
    }
}

// ---------------- alpha: E = out1 . wa ; softmax over seq ----------------
__global__ __launch_bounds__(256) void alpha_kernel(const float* __restrict__ wa) {
    const int b = blockIdx.x;
    __shared__ float was[256];
    __shared__ float Es[224];
    __shared__ float red[256];
    const int tid = threadIdx.x;
    was[tid] = wa[tid];
    __syncthreads();
    const int warp = tid >> 5, lane = tid & 31;
    for (int s = warp; s < SS; s += 8) {
        float p = 0.f;
        const float* hb = g_hs[0] + (size_t)s * HH * BB + b;
#pragma unroll 8
        for (int j = lane; j < HH; j += 32) p += hb[j * BB] * was[j];
#pragma unroll
        for (int off = 16; off; off >>= 1) p += __shfl_xor_sync(0xffffffffu, p, off);
        if (lane == 0) Es[s] = p;
    }
    __syncthreads();
    float v = (tid < SS) ? Es[tid] : -3.4e38f;
    red[tid] = v;
    __syncthreads();
    for (int off = 128; off; off >>= 1) {
        if (tid < off) red[tid] = fmaxf(red[tid], red[tid + off]);
        __syncthreads();
    }
    const float mx = red[0];
    __syncthreads();
    float e = (tid < SS) ? __expf(Es[tid] - mx) : 0.f;
    red[tid] = e;
    __syncthreads();
    for (int off = 128; off; off >>= 1) {
        if (tid < off) red[tid] += red[tid + off];
        __syncthreads();
    }
    const float sum = red[0];
    if (tid < SS) g_alpha[b * SS + tid] = e / sum;
}

// ---------------- Beta: tanh(Wb @ out2_s^T), per s.  M=256(d) N=128(b) K=256(h) ----------------
__global__ __launch_bounds__(256) void beta_gemm(const float* __restrict__ Wb) {
    const int s  = blockIdx.z;
    const int d0 = blockIdx.y * 128;
    const int n0 = blockIdx.x * 64;
    __shared__ __align__(16) float As[16][128];
    __shared__ __align__(16) float Bs[16][64];
    const int tid = threadIdx.x;
    const int a_m = tid >> 1, a_k = (tid & 1) * 8;
    const int b_k = tid >> 4, b_n = (tid & 15) * 4;
    const int tx = tid & 15, ty = tid >> 4;
    unsigned long long accp[4][4];
#pragma unroll
    for (int ip = 0; ip < 4; ++ip)
#pragma unroll
        for (int jx = 0; jx < 4; ++jx) accp[ip][jx] = 0ULL;

    const float* Ap = Wb + (size_t)(d0 + a_m) * HH + a_k;
    const float* Bp = g_hs[1] + (size_t)s * HH * BB + b_k * BB + n0 + b_n;

    for (int k0 = 0; k0 < HH; k0 += 16) {
        float4 av0 = *(const float4*)(Ap + k0);
        float4 av1 = *(const float4*)(Ap + k0 + 4);
        float4 bv  = *(const float4*)(Bp + (size_t)k0 * BB);
        __syncthreads();
        As[a_k + 0][a_m] = av0.x; As[a_k + 1][a_m] = av0.y;
        As[a_k + 2][a_m] = av0.z; As[a_k + 3][a_m] = av0.w;
        As[a_k + 4][a_m] = av1.x; As[a_k + 5][a_m] = av1.y;
        As[a_k + 6][a_m] = av1.z; As[a_k + 7][a_m] = av1.w;
        *(float4*)&Bs[b_k][b_n] = bv;
        __syncthreads();
#pragma unroll
        for (int k = 0; k < 16; ++k) {
            const unsigned long long* ap = (const unsigned long long*)&As[k][ty * 8];
            const float* bqf = &Bs[k][tx * 4];
            unsigned long long b2[4];
            DUP2(b2[0], bqf[0]); DUP2(b2[1], bqf[1]);
            DUP2(b2[2], bqf[2]); DUP2(b2[3], bqf[3]);
#pragma unroll
            for (int ip = 0; ip < 4; ++ip) {
                unsigned long long a2 = ap[ip];
#pragma unroll
                for (int jx = 0; jx < 4; ++jx) FMA2(accp[ip][jx], a2, b2[jx]);
            }
        }
    }
#pragma unroll
    for (int ip = 0; ip < 4; ++ip) {
        int d = d0 + ty * 8 + 2 * ip;
        float4 v0 = make_float4(tanhf(lo2(accp[ip][0])), tanhf(lo2(accp[ip][1])),
                                tanhf(lo2(accp[ip][2])), tanhf(lo2(accp[ip][3])));
        float4 v1 = make_float4(tanhf(hi2(accp[ip][0])), tanhf(hi2(accp[ip][1])),
                                tanhf(hi2(accp[ip][2])), tanhf(hi2(accp[ip][3])));
        *(float4*)&g_beta[((size_t)s * DD + d) * BB + n0 + tx * 4] = v0;
        *(float4*)&g_beta[((size_t)s * DD + d + 1) * BB + n0 + tx * 4] = v1;
    }
}

// ---------------- ctx[b][d] = sum_s embedded[b][s][d] * beta[s][d][b] * alpha[b][s] ----------------
__global__ __launch_bounds__(128) void ctx_kernel() {
    const int d = blockIdx.x;
    const int b = threadIdx.x;
    float acc = 0.f;
    const float* em = g_embedded + (size_t)b * (SS * DD) + d;
    const float* bt = g_beta + (size_t)d * BB + b;
    const float* al = g_alpha + b * SS;
    for (int s = 0; s < SS; ++s)
        acc += em[(size_t)s * DD] * bt[(size_t)s * DD * BB] * al[s];
    g_ctx[b * DD + d] = acc;
}

// ---------------- out = ctx @ Wout^T ----------------
__global__ __launch_bounds__(128) void out_kernel(const float* __restrict__ Wout,
                                                  float* __restrict__ out) {
    const int b = blockIdx.x;
    const int n = threadIdx.x;
    __shared__ float cs[256];
    cs[n] = g_ctx[b * DD + n];
    cs[n + 128] = g_ctx[b * DD + n + 128];
    __syncthreads();
    float acc = 0.f;
    const float4* wp = (const float4*)(Wout + (size_t)n * DD);
#pragma unroll 8
    for (int d4 = 0; d4 < 64; ++d4) {
        float4 w = wp[d4];
        acc += cs[4 * d4] * w.x + cs[4 * d4 + 1] * w.y +
               cs[4 * d4 + 2] * w.z + cs[4 * d4 + 3] * w.w;
    }
    out[b * NC + n] = acc;
}

// ---------------- launch ----------------
extern "C" void kernel_launch(void* const* d_in, const int* in_sizes, int n_in,
                              void* d_out, int out_size) {
    (void)in_sizes; (void)n_in; (void)out_size;
    const float* inputs  = (const float*)d_in[0];
    const float* tstamp  = (const float*)d_in[1];
    const float* emb     = (const float*)d_in[2];
    const float* Wall1_w = (const float*)d_in[3];
    const float* Wall1_b = (const float*)d_in[4];
    const float* Uall1_w = (const float*)d_in[5];
    const float* Uall1_b = (const float*)d_in[6];
    const float* Wd1_w   = (const float*)d_in[7];
    const float* Wd1_b   = (const float*)d_in[8];
    const float* Wall2_w = (const float*)d_in[9];
    const float* Wall2_b = (const float*)d_in[10];
    const float* Uall2_w = (const float*)d_in[11];
    const float* Uall2_b = (const float*)d_in[12];
    const float* Wd2_w   = (const float*)d_in[13];
    const float* Wd2_b   = (const float*)d_in[14];
    const float* wa_w    = (const float*)d_in[15];
    const float* Wb_w    = (const float*)d_in[16];
    const float* Wout_w  = (const float*)d_in[17];
    const float* h01     = (const float*)d_in[18];
    const float* c01     = (const float*)d_in[19];
    const float* h02     = (const float*)d_in[20];
    const float* c02     = (const float*)d_in[21];
    float* out = (float*)d_out;

    init_kernel<<<128, 256>>>(h01, c01, h02, c02, tstamp);
    embed_gemm<<<dim3(4, 200), 256>>>(inputs, emb);
    ux_gemm<<<dim3(2, 8, 2 * SS), 256>>>(Uall1_w, Uall1_b, Wall1_b,
                                         Uall2_w, Uall2_b, Wall2_b);

    // persistent recurrence: cooperative launch, 84 KB dynamic smem
    {
        const size_t dyn = (5120 + 256 * 21) * sizeof(unsigned long long); // 83968
        static int attr_set = 0;
        if (!attr_set) {
            cudaFuncSetAttribute(recur_kernel,
                                 cudaFuncAttributeMaxDynamicSharedMemorySize, (int)dyn);
            attr_set = 1;
        }
        cudaLaunchConfig_t cfg = {};
        cfg.gridDim = dim3(NBLK, 1, 1);
        cfg.blockDim = dim3(512, 1, 1);
        cfg.dynamicSmemBytes = dyn;
        cfg.stream = 0;
        cudaLaunchAttribute attrs[1];
        attrs[0].id = cudaLaunchAttributeCooperative;
        attrs[0].val.cooperative = 1;
        cfg.attrs = attrs;
        cfg.numAttrs = 1;
        cudaLaunchKernelEx(&cfg, recur_kernel,
                           Wall1_w, Wd1_w, Wd1_b, Wall2_w, Wd2_w, Wd2_b);
    }

    alpha_kernel<<<128, 256>>>(wa_w);
    beta_gemm<<<dim3(2, 2, SS), 256>>>(Wb_w);
    ctx_kernel<<<256, 128>>>();
    out_kernel<<<128, 128>>>(Wout_w, out);
}